// round 13
// baseline (speedup 1.0000x reference)
#include <cuda_runtime.h>
#include <cuda_bf16.h>
#include <math.h>
#include <stdint.h>

#define S_LEN  2048
#define DMODEL 2048
#define NHEADS 16
#define HD     128
#define KVH    4
#define KVD    512
#define QKVW   3072   // 2048 q + 512 k + 512 v

// ---------------- fp32 intermediates ----------------
__device__ float g_part[2][S_LEN * QKVW];   // split-K partials of QKV projection
__device__ float g_v[S_LEN * KVD];          // summed V (compact)

// ---------------- packed quad images ----------------
// Matrix [R][K] K-major: quad t = r*(K/32)*8 + ch*8 + q, q = ks*4+s,
// k0 = ch*32+ks*16+s*2; quad = {hi(k0,k0+1), hi(k0+8,k0+9), lo(..), lo(..)}.
__device__ uint4 xq_[1048576];     // x [2048][2048]
__device__ uint4 wqkvq_[1572864];  // [3072][2048]
__device__ uint4 wpq_[1048576];
__device__ uint4 qq_[1048576];     // q roped*gain*scale*log2e, rows h*2048+s, K=128
__device__ uint4 kq_[262144];      // k roped, rows kv*2048+s, K=128
__device__ uint4 vtq_[262144];     // V^T, rows kv*128+d, K=2048
__device__ uint4 yq_[1048576];     // y rejected [2048][2048]

// ---------------- helpers ----------------
__device__ __forceinline__ float ex2(float x) {
    float r;
    asm("ex2.approx.f32 %0, %1;" : "=f"(r) : "f"(x));
    return r;
}

__device__ __forceinline__ void cvtpair(float x, float y, uint32_t& hi, uint32_t& lo) {
    asm("cvt.rn.bf16x2.f32 %0, %1, %2;" : "=r"(hi) : "f"(y), "f"(x));
    float xr = x - __uint_as_float(hi << 16);
    float yr = y - __uint_as_float(hi & 0xffff0000u);
    asm("cvt.rn.bf16x2.f32 %0, %1, %2;" : "=r"(lo) : "f"(yr), "f"(xr));
}

__device__ __forceinline__ uint4 pack_quad(float f0, float f1, float f2, float f3) {
    uint32_t h0, l0, h1, l1;
    cvtpair(f0, f1, h0, l0);
    cvtpair(f2, f3, h1, l1);
    return make_uint4(h0, h1, l0, l1);
}

__device__ __forceinline__ uint32_t s2u(const void* p) {
    uint32_t a;
    asm("{ .reg .u64 t; cvta.to.shared.u64 t, %1; cvt.u32.u64 %0, t; }" : "=r"(a) : "l"(p));
    return a;
}

__device__ __forceinline__ void cpa16(void* dst, const void* src) {
    asm volatile("cp.async.cg.shared.global [%0], [%1], 16;"
                 :: "r"(s2u(dst)), "l"(src) : "memory");
}
#define CPA_COMMIT() asm volatile("cp.async.commit_group;" ::: "memory")
#define CPA_WAIT0()  asm volatile("cp.async.wait_group 0;" ::: "memory")
#define CPA_WAIT1()  asm volatile("cp.async.wait_group 1;" ::: "memory")

__device__ __forceinline__ void mma_bf16(float* c, const uint32_t* a, const uint32_t* b) {
    asm volatile(
        "mma.sync.aligned.m16n8k16.row.col.f32.bf16.bf16.f32 "
        "{%0,%1,%2,%3}, {%4,%5,%6,%7}, {%8,%9}, {%0,%1,%2,%3};\n"
        : "+f"(c[0]), "+f"(c[1]), "+f"(c[2]), "+f"(c[3])
        : "r"(a[0]), "r"(a[1]), "r"(a[2]), "r"(a[3]),
          "r"(b[0]), "r"(b[1]));
}

// ---------------- merged K-major pack (5 matrices, one launch) ----------------
struct PackJobs {
    const float* src[5];
    uint4*       dst[5];
    int          total[5];
};

__global__ void pack_all(PackJobs jobs)
{
    const int seg = blockIdx.y;
    int t = blockIdx.x * 256 + threadIdx.x;
    if (t >= jobs.total[seg]) return;
    int r = t >> 9;              // 512 quads/row (K=2048)
    int G = t & 511;
    int ch = G >> 3, q = G & 7;
    int k0 = ch * 32 + (q >> 2) * 16 + (q & 3) * 2;
    const float* p = jobs.src[seg] + (size_t)r * DMODEL + k0;
    jobs.dst[seg][t] = pack_quad(p[0], p[1], p[8], p[9]);
}

// ---------------- v sum: g_v = part0 + part1 (v columns, compact) ----------------
__global__ void vsum()
{
    int idx = blockIdx.x * 256 + threadIdx.x;    // over 2048*512/4
    if (idx >= S_LEN * KVD / 4) return;
    int s = idx / (KVD / 4);
    int c = (idx - s * (KVD / 4)) * 4;
    size_t o = (size_t)s * QKVW + 2560 + c;
    float4 a = *(const float4*)(g_part[0] + o);
    float4 b = *(const float4*)(g_part[1] + o);
    *(float4*)(g_v + (size_t)s * KVD + c) =
        make_float4(a.x + b.x, a.y + b.y, a.z + b.z, a.w + b.w);
}

// ---------------- V^T pack: rows kv*128+d, K = sequence ----------------
__global__ void pack_vt()
{
    int t = blockIdx.x * 256 + threadIdx.x;   // 262144
    int q = t & 7, ch = (t >> 3) & 63;
    int d = (t >> 9) & 127, kv = t >> 16;
    int k0 = ch * 32 + (q >> 2) * 16 + (q & 3) * 2;
    const float* p = g_v + (size_t)k0 * KVD + kv * HD + d;
    vtq_[t] = pack_quad(p[0], p[KVD], p[8 * KVD], p[9 * KVD]);
}

// =============================================================
// bf16 3-pass GEMM, NT on packed images.
// mode: 2 = causal skip, 4 = triangular K, 8 = split-K (z = K-half)
// =============================================================
#define SST 48
#define STAGE_U32 (2 * 128 * SST)
#define GSMEM_BYTES (2 * STAGE_U32 * 4)

__global__ void __launch_bounds__(256, 2)
gemm_pk(const uint4* __restrict__ Aq, int aRow, size_t aZ,
        const uint4* __restrict__ Bq, int bRow, size_t bZ, int bshift,
        float* __restrict__ C, int ldc, size_t cZ,
        int nChTot, float alpha, int mode)
{
    const int bm = blockIdx.y, bn = blockIdx.x, z = blockIdx.z;
    if ((mode & 2) && bn > bm) return;
    const int nCh = (mode & 4) ? min(nChTot, (bm + 1) * 4) : nChTot;
    const int chBase = (mode & 8) ? z * nChTot : 0;

    extern __shared__ uint32_t smu[];
    const int tid = threadIdx.x, lane = tid & 31, wid = tid >> 5;
    const int wm = (wid >> 2) * 64, wn = (wid & 3) * 32;
    const int g8 = lane >> 2, tig = lane & 3;

    const uint4* Ab;
    const uint4* Bb;
    if (mode & 8) {
        Ab = Aq + (size_t)bm * 128 * aRow;
        Bb = Bq + (size_t)bn * 128 * bRow;
    } else {
        Ab = Aq + z * aZ + (size_t)bm * 128 * aRow;
        Bb = Bq + (size_t)(z >> bshift) * bZ + (size_t)bn * 128 * bRow;
    }

    float acc[4][4][4] = {};

    auto loadStage = [&](int ch, int st) {
        uint32_t* base = smu + st * STAGE_U32;
#pragma unroll
        for (int i = 0; i < 8; i++) {
            int idx = tid + i * 256;
            int op = idx >> 10, rem = idx & 1023;
            int row = rem >> 3, q = rem & 7;
            const uint4* src = (op ? Bb + (size_t)row * bRow
                                   : Ab + (size_t)row * aRow) + (chBase + ch) * 8 + q;
            cpa16(base + op * (128 * SST) + row * SST + q * 4, src);
        }
        CPA_COMMIT();
    };

    auto compute = [&](int st) {
        const uint32_t* As = smu + st * STAGE_U32;
        const uint32_t* Bs = As + 128 * SST;
#pragma unroll
        for (int g = 0; g < 2; g++) {
            uint32_t aH[4][4], aL[4][4], bH[4][2], bL[4][2];
#pragma unroll
            for (int mf = 0; mf < 4; mf++) {
                int r0 = wm + mf * 16 + g8;
                uint4 q0 = *(const uint4*)(As + r0 * SST + g * 16 + tig * 4);
                uint4 q1 = *(const uint4*)(As + (r0 + 8) * SST + g * 16 + tig * 4);
                aH[mf][0] = q0.x; aH[mf][1] = q1.x; aH[mf][2] = q0.y; aH[mf][3] = q1.y;
                aL[mf][0] = q0.z; aL[mf][1] = q1.z; aL[mf][2] = q0.w; aL[mf][3] = q1.w;
            }
#pragma unroll
            for (int nf = 0; nf < 4; nf++) {
                int n = wn + nf * 8 + g8;
                uint4 q = *(const uint4*)(Bs + n * SST + g * 16 + tig * 4);
                bH[nf][0] = q.x; bH[nf][1] = q.y;
                bL[nf][0] = q.z; bL[nf][1] = q.w;
            }
#pragma unroll
            for (int mf = 0; mf < 4; mf++)
#pragma unroll
                for (int nf = 0; nf < 4; nf++) {
                    mma_bf16(acc[mf][nf], aL[mf], bH[nf]);
                    mma_bf16(acc[mf][nf], aH[mf], bL[nf]);
                    mma_bf16(acc[mf][nf], aH[mf], bH[nf]);
                }
        }
    };

    loadStage(0, 0);
    for (int it = 0; it < nCh; ++it) {
        int cur = it & 1;
        if (it + 1 < nCh) { loadStage(it + 1, cur ^ 1); CPA_WAIT1(); }
        else              { CPA_WAIT0(); }
        __syncthreads();
        compute(cur);
        __syncthreads();
    }

    float* Cb = C + z * cZ + (size_t)bm * 128 * ldc + bn * 128;
#pragma unroll
    for (int mf = 0; mf < 4; mf++) {
        int row0 = wm + mf * 16 + g8, row1 = row0 + 8;
#pragma unroll
        for (int nf = 0; nf < 4; nf++) {
            int col = wn + nf * 8 + tig * 2;
            *(float2*)(Cb + (size_t)row0 * ldc + col) =
                make_float2(acc[mf][nf][0] * alpha, acc[mf][nf][1] * alpha);
            *(float2*)(Cb + (size_t)row1 * ldc + col) =
                make_float2(acc[mf][nf][2] * alpha, acc[mf][nf][3] * alpha);
        }
    }
}

// ---------------- RMSNorm + RoPE over summed partials -> packed images ----------------
__global__ void rope_both(const float* __restrict__ gain, float qscale)
{
    __shared__ float stg[4][128];
    const int wib = threadIdx.x >> 5;
    const int lane = threadIdx.x & 31;
    const int isK = blockIdx.y;
    const int w = blockIdx.x * 4 + wib;
    int nh, coff;
    uint4* img;
    if (isK) {
        if (w >= S_LEN * KVH) return;
        nh = KVH; coff = 2048; img = kq_;
    } else {
        nh = NHEADS; coff = 0; img = qq_;
    }
    const int s = w / nh, h = w - (w / nh) * nh;
    if (s >= S_LEN) return;

    size_t o = (size_t)s * QKVW + coff + h * HD;
    const float* p0 = g_part[0] + o;
    const float* p1 = g_part[1] + o;
    float2 a1 = *(const float2*)(p0 + 2 * lane);
    float2 b1 = *(const float2*)(p1 + 2 * lane);
    float2 a2 = *(const float2*)(p0 + 64 + 2 * lane);
    float2 b2 = *(const float2*)(p1 + 64 + 2 * lane);
    float2 u1 = make_float2(a1.x + b1.x, a1.y + b1.y);
    float2 u2 = make_float2(a2.x + b2.x, a2.y + b2.y);

    float ss = u1.x * u1.x + u1.y * u1.y + u2.x * u2.x + u2.y * u2.y;
#pragma unroll
    for (int off = 16; off; off >>= 1) ss += __shfl_xor_sync(0xffffffffu, ss, off);
    const float r = rsqrtf(ss * (1.f / 128.f) + 1.1920929e-07f);
    const float g = isK ? 1.0f : gain[h] * qscale;
    float x1a = u1.x * r, x1b = u1.y * r, x2a = u2.x * r, x2b = u2.y * r;
    const float kln = 9.210340371976184f / 128.f;
    float th0 = (float)s * expf(-(float)(4 * lane) * kln);
    float th1 = (float)s * expf(-(float)(4 * lane + 2) * kln);
    float c0, s0, c1, s1;
    sincosf(th0, &s0, &c0);
    sincosf(th1, &s1, &c1);
    stg[wib][2 * lane]          = (x1a * c0 + x2a * s0) * g;
    stg[wib][2 * lane + 1]      = (x1b * c1 + x2b * s1) * g;
    stg[wib][64 + 2 * lane]     = (x2a * c0 - x1a * s0) * g;
    stg[wib][64 + 2 * lane + 1] = (x2b * c1 - x1b * s1) * g;
    __syncwarp();
    int ch = lane >> 3, q = lane & 7;
    int k0 = ch * 32 + (q >> 2) * 16 + (q & 3) * 2;
    const float* sp = &stg[wib][0];
    img[(size_t)(h * S_LEN + s) * 32 + lane] =
        pack_quad(sp[k0], sp[k0 + 1], sp[k0 + 8], sp[k0 + 9]);
}

// =============================================================
// Fused flash attention + v-rejection + y pack (log2 domain, ex2).
// =============================================================
#define FL_SMEM (3 * 4096 * 16)

__global__ void __launch_bounds__(256, 1)
flash_attn()
{
    extern __shared__ uint4 fsm[];
    uint4* sQ = fsm;
    uint4* sK = fsm + 4096;
    uint4* sV = fsm + 8192;

    const int bid = blockIdx.x;
    const int qb = 15 - (bid >> 4);
    const int h  = bid & 15;
    const int kv = h >> 2;
    const int tid = threadIdx.x, lane = tid & 31, wid = tid >> 5;
    const int g8 = lane >> 2, tig = lane & 3;
    const int mr = wid * 16;

    {
        const uint4* Qg = qq_ + ((size_t)h * S_LEN + qb * 128) * 32;
        const uint4* Kg = kq_ + ((size_t)kv * S_LEN) * 32;
#pragma unroll
        for (int i = 0; i < 16; i++) { int idx = tid + i * 256; cpa16(&sQ[idx], &Qg[idx]); }
#pragma unroll
        for (int i = 0; i < 16; i++) { int idx = tid + i * 256; cpa16(&sK[idx], &Kg[idx]); }
        CPA_COMMIT(); CPA_WAIT0(); __syncthreads();
    }

    float sAcc[16][4];
    float oAcc[16][4] = {};
    float mA = -INFINITY, mB = -INFINITY, lA = 0.f, lB = 0.f;

    for (int kb = 0; kb <= qb; kb++) {
#pragma unroll
        for (int i = 0; i < 16; i++) {
            int idx = tid + i * 256;
            int row = idx >> 5, lq = idx & 31;
            cpa16(&sV[row * 32 + lq],
                  &vtq_[((size_t)(kv * 128 + row)) * 512 + kb * 32 + lq]);
        }
        CPA_COMMIT();

#pragma unroll
        for (int nf = 0; nf < 16; nf++)
#pragma unroll
            for (int e = 0; e < 4; e++) sAcc[nf][e] = 0.f;
#pragma unroll
        for (int c = 0; c < 8; c++) {
            int qoff = (c >> 1) * 8 + (c & 1) * 4 + tig;
            uint4 q0 = sQ[(mr + g8) * 32 + qoff];
            uint4 q1 = sQ[(mr + g8 + 8) * 32 + qoff];
            uint32_t aH[4] = {q0.x, q1.x, q0.y, q1.y};
            uint32_t aL[4] = {q0.z, q1.z, q0.w, q1.w};
#pragma unroll
            for (int nf = 0; nf < 16; nf++) {
                uint4 kq4 = sK[(nf * 8 + g8) * 32 + qoff];
                uint32_t bH[2] = {kq4.x, kq4.y}, bL[2] = {kq4.z, kq4.w};
                mma_bf16(sAcc[nf], aL, bH);
                mma_bf16(sAcc[nf], aH, bL);
                mma_bf16(sAcc[nf], aH, bH);
            }
        }

        if (kb == qb) {
            int rA = mr + g8, rB = rA + 8;
#pragma unroll
            for (int nf = 0; nf < 16; nf++) {
                int c0 = nf * 8 + tig * 2;
                if (c0     > rA) sAcc[nf][0] = -INFINITY;
                if (c0 + 1 > rA) sAcc[nf][1] = -INFINITY;
                if (c0     > rB) sAcc[nf][2] = -INFINITY;
                if (c0 + 1 > rB) sAcc[nf][3] = -INFINITY;
            }
        }

        float mlA = -INFINITY, mlB = -INFINITY;
#pragma unroll
        for (int nf = 0; nf < 16; nf++) {
            mlA = fmaxf(mlA, fmaxf(sAcc[nf][0], sAcc[nf][1]));
            mlB = fmaxf(mlB, fmaxf(sAcc[nf][2], sAcc[nf][3]));
        }
        mlA = fmaxf(mlA, __shfl_xor_sync(0xffffffffu, mlA, 1));
        mlA = fmaxf(mlA, __shfl_xor_sync(0xffffffffu, mlA, 2));
        mlB = fmaxf(mlB, __shfl_xor_sync(0xffffffffu, mlB, 1));
        mlB = fmaxf(mlB, __shfl_xor_sync(0xffffffffu, mlB, 2));
        float mnA = fmaxf(mA, mlA), mnB = fmaxf(mB, mlB);
        float alA = ex2(mA - mnA), alB = ex2(mB - mnB);
        mA = mnA; mB = mnB;
        float rsA = 0.f, rsB = 0.f;
#pragma unroll
        for (int nf = 0; nf < 16; nf++) {
            float p0 = ex2(sAcc[nf][0] - mnA);
            float p1 = ex2(sAcc[nf][1] - mnA);
            float p2 = ex2(sAcc[nf][2] - mnB);
            float p3 = ex2(sAcc[nf][3] - mnB);
            sAcc[nf][0] = p0; sAcc[nf][1] = p1; sAcc[nf][2] = p2; sAcc[nf][3] = p3;
            rsA += p0 + p1; rsB += p2 + p3;
        }
        rsA += __shfl_xor_sync(0xffffffffu, rsA, 1);
        rsA += __shfl_xor_sync(0xffffffffu, rsA, 2);
        rsB += __shfl_xor_sync(0xffffffffu, rsB, 1);
        rsB += __shfl_xor_sync(0xffffffffu, rsB, 2);
        lA = lA * alA + rsA;
        lB = lB * alB + rsB;
#pragma unroll
        for (int nf = 0; nf < 16; nf++) {
            oAcc[nf][0] *= alA; oAcc[nf][1] *= alA;
            oAcc[nf][2] *= alB; oAcc[nf][3] *= alB;
        }

        CPA_WAIT0(); __syncthreads();

        if (kb < qb) {
            const uint4* Kg = kq_ + ((size_t)kv * S_LEN + (kb + 1) * 128) * 32;
#pragma unroll
            for (int i = 0; i < 16; i++) { int idx = tid + i * 256; cpa16(&sK[idx], &Kg[idx]); }
            CPA_COMMIT();
        }

#pragma unroll
        for (int c = 0; c < 8; c++) {
            uint32_t aH[4], aL[4];
            cvtpair(sAcc[2 * c][0],     sAcc[2 * c][1],     aH[0], aL[0]);
            cvtpair(sAcc[2 * c][2],     sAcc[2 * c][3],     aH[1], aL[1]);
            cvtpair(sAcc[2 * c + 1][0], sAcc[2 * c + 1][1], aH[2], aL[2]);
            cvtpair(sAcc[2 * c + 1][2], sAcc[2 * c + 1][3], aH[3], aL[3]);
            int qoff = (c >> 1) * 8 + (c & 1) * 4 + tig;
#pragma unroll
            for (int nf = 0; nf < 16; nf++) {
                uint4 v4 = sV[(nf * 8 + g8) * 32 + qoff];
                uint32_t bH[2] = {v4.x, v4.y}, bL[2] = {v4.z, v4.w};
                mma_bf16(oAcc[nf], aL, bH);
                mma_bf16(oAcc[nf], aH, bL);
                mma_bf16(oAcc[nf], aH, bH);
            }
        }

        if (kb < qb) { CPA_WAIT0(); __syncthreads(); }
    }

    // ---- epilogue ----
    __syncthreads();
    float* Ob = (float*)sK;
    float invA = 1.f / lA, invB = 1.f / lB;
#pragma unroll
    for (int nf = 0; nf < 16; nf++) {
        int col = nf * 8 + tig * 2;
        Ob[(mr + g8) * 132 + col]         = oAcc[nf][0] * invA;
        Ob[(mr + g8) * 132 + col + 1]     = oAcc[nf][1] * invA;
        Ob[(mr + g8 + 8) * 132 + col]     = oAcc[nf][2] * invB;
        Ob[(mr + g8 + 8) * 132 + col + 1] = oAcc[nf][3] * invB;
    }
    __syncthreads();

    const float* gv = g_v + kv * HD;
    for (int r16 = 0; r16 < 16; r16++) {
        int r = mr + r16;
        int sg = qb * 128 + r;
        float4 vv = *(const float4*)(gv + (size_t)sg * KVD + lane * 4);
        float4 yy = *(float4*)(Ob + r * 132 + lane * 4);
        float vsq = vv.x * vv.x + vv.y * vv.y + vv.z * vv.z + vv.w * vv.w;
        float yv  = yy.x * vv.x + yy.y * vv.y + yy.z * vv.z + yy.w * vv.w;
#pragma unroll
        for (int off = 16; off; off >>= 1) {
            vsq += __shfl_xor_sync(0xffffffffu, vsq, off);
            yv  += __shfl_xor_sync(0xffffffffu, yv, off);
        }
        float mx = fmaxf(sqrtf(vsq), 1e-12f);
        float c2 = yv / (mx * mx);
        yy.x -= c2 * vv.x; yy.y -= c2 * vv.y; yy.z -= c2 * vv.z; yy.w -= c2 * vv.w;
        *(float4*)(Ob + r * 132 + lane * 4) = yy;
        __syncwarp();
        int ch = lane >> 3, ks = (lane >> 2) & 1, sq = lane & 3;
        int k0 = ch * 32 + ks * 16 + sq * 2;
        yq_[(size_t)sg * 512 + (h * 4 + ch) * 8 + ks * 4 + sq] =
            pack_quad(Ob[r * 132 + k0], Ob[r * 132 + k0 + 1],
                      Ob[r * 132 + k0 + 8], Ob[r * 132 + k0 + 9]);
        __syncwarp();
    }
}

// ---------------- v output transpose ----------------
__global__ void v_transpose_kernel(float* __restrict__ out)
{
    int idx = blockIdx.x * blockDim.x + threadIdx.x;
    if (idx < S_LEN * KVD / 4) {
        int f = idx * 4;
        int s = f / KVD, rem = f % KVD;
        int kvh = rem / HD, d = rem % HD;
        float4 val = *(const float4*)(g_v + f);
        *(float4*)(out + (size_t)kvh * S_LEN * HD + (size_t)s * HD + d) = val;
    }
}

// ---------------- launch ----------------
extern "C" void kernel_launch(void* const* d_in, const int* in_sizes, int n_in,
                              void* d_out, int out_size)
{
    int big[3], nbig = 0, med[2], nmed = 0, gidx = -1;
    for (int i = 0; i < n_in && i < 6; i++) {
        int sz = in_sizes[i];
        if (sz == NHEADS) gidx = i;
        else if (sz == S_LEN * KVD) { if (nmed < 2) med[nmed++] = i; }
        else { if (nbig < 3) big[nbig++] = i; }
    }
    int ix, iwq, iwk, iwv, iwp, ig;
    ig  = (gidx >= 0) ? gidx : 5;
    iwk = (nmed > 0) ? med[0] : 2;
    iwv = (nmed > 1) ? med[1] : 3;
    if (ig == 5) { ix = big[0]; iwq = big[1]; iwp = big[2]; }
    else         { iwp = big[0]; iwq = big[1]; ix = big[2]; }

    const float* x  = (const float*)d_in[ix];
    const float* Wq = (const float*)d_in[iwq];
    const float* Wk = (const float*)d_in[iwk];
    const float* Wv = (const float*)d_in[iwv];
    const float* Wp = (const float*)d_in[iwp];
    const float* qg = (const float*)d_in[ig];
    float* out = (float*)d_out;

    float* ppart;
    cudaGetSymbolAddress((void**)&ppart, g_part);
    uint4 *ixq, *iwqkv, *iwpq, *iyq;
    cudaGetSymbolAddress((void**)&ixq,   xq_);
    cudaGetSymbolAddress((void**)&iwqkv, wqkvq_);
    cudaGetSymbolAddress((void**)&iwpq,  wpq_);
    cudaGetSymbolAddress((void**)&iyq,   yq_);

    cudaFuncSetAttribute(gemm_pk, cudaFuncAttributeMaxDynamicSharedMemorySize, GSMEM_BYTES);
    cudaFuncSetAttribute(flash_attn, cudaFuncAttributeMaxDynamicSharedMemorySize, FL_SMEM);
    (void)cudaGetLastError();

    const float scale = 0.08838834764831845f;          // 1/sqrt(128)
    const float qscale = scale * 1.4426950408889634f;  // fold log2(e)

    // one launch for all 5 packs
    PackJobs jobs;
    jobs.src[0] = x;  jobs.dst[0] = ixq;                         jobs.total[0] = 1048576;
    jobs.src[1] = Wq; jobs.dst[1] = iwqkv;                       jobs.total[1] = 1048576;
    jobs.src[2] = Wp; jobs.dst[2] = iwpq;                        jobs.total[2] = 1048576;
    jobs.src[3] = Wk; jobs.dst[3] = iwqkv + (size_t)2048 * 512;  jobs.total[3] = 262144;
    jobs.src[4] = Wv; jobs.dst[4] = iwqkv + (size_t)2560 * 512;  jobs.total[4] = 262144;
    pack_all<<<dim3(4096, 5), 256>>>(jobs);

    // fused QKV projection, split-K=2 -> partials
    gemm_pk<<<dim3(24, 16, 2), 256, GSMEM_BYTES>>>(ixq, 512, 0, iwqkv, 512, 0, 0,
                                                   ppart, QKVW, (size_t)S_LEN * QKVW,
                                                   32, 1.0f, 8);

    // v = part0+part1 ; rmsnorm+rope over partial sums -> packed q/k ; V^T pack
    vsum<<<(S_LEN * KVD / 4 + 255) / 256, 256>>>();
    rope_both<<<dim3((S_LEN * NHEADS) / 4, 2), 128>>>(qg, qscale);
    pack_vt<<<1024, 256>>>();

    // fused flash attention (+ v-rejection + y pack)
    flash_attn<<<256, 256, FL_SMEM>>>();

    // output projection
    gemm_pk<<<dim3(16, 16, 1), 256, GSMEM_BYTES>>>(iyq, 512, 0, iwpq, 512, 0, 0,
                                                   out, DMODEL, 0, 64, 1.0f, 0);

    // v second output
    if (out_size >= S_LEN * DMODEL + S_LEN * KVD)
        v_transpose_kernel<<<(S_LEN * KVD / 4 + 255) / 256, 256>>>(out + (size_t)S_LEN * DMODEL);
}

// round 16
// speedup vs baseline: 1.4257x; 1.4257x over previous
#include <cuda_runtime.h>
#include <cuda_bf16.h>
#include <cuda_fp16.h>
#include <math.h>
#include <stdint.h>

#define S_LEN  2048
#define DMODEL 2048
#define NHEADS 16
#define HD     128
#define KVH    4
#define KVD    512
#define QKVW   3072   // 2048 q + 512 k + 512 v

// ---------------- fp32 intermediates ----------------
__device__ float g_qkv[S_LEN * QKVW];   // fused projection output

// ---------------- packed images ----------------
// Quad image (hi/lo, 4 elems per uint4): t = r*(K/32)*8 + ch*8 + q, q=ks*4+s,
//   k0 = ch*32+ks*16+s*2; quad = {hi(k0,k0+1), hi(k0+8,k0+9), lo(..), lo(..)}
// Pair image (hi only, 4 elems per uint2): same t indexing, {hi(k0,k0+1), hi(k0+8,k0+9)}
__device__ uint2 xq2_[1048576];    // x, fp16 hi-only [2048][2048]
__device__ uint4 wqkvq_[1572864];  // fp16 hi/lo [3072][2048]
__device__ uint4 wpq_[1048576];    // fp16 hi/lo
__device__ uint2 yq2_[1048576];    // y, fp16 hi-only [2048][2048]
__device__ uint4 qq_[1048576];     // bf16 q roped*gain*scale*log2e, rows h*2048+s, K=128
__device__ uint4 kq_[262144];      // bf16 k roped, rows kv*2048+s, K=128
__device__ uint4 vtq_[262144];     // bf16 V^T, rows kv*128+d, K=2048

// ---------------- helpers ----------------
__device__ __forceinline__ float ex2(float x) {
    float r;
    asm("ex2.approx.f32 %0, %1;" : "=f"(r) : "f"(x));
    return r;
}

// bf16 hi/lo (flash path, unchanged semantics)
__device__ __forceinline__ void cvtpair(float x, float y, uint32_t& hi, uint32_t& lo) {
    asm("cvt.rn.bf16x2.f32 %0, %1, %2;" : "=r"(hi) : "f"(y), "f"(x));
    float xr = x - __uint_as_float(hi << 16);
    float yr = y - __uint_as_float(hi & 0xffff0000u);
    asm("cvt.rn.bf16x2.f32 %0, %1, %2;" : "=r"(lo) : "f"(yr), "f"(xr));
}

__device__ __forceinline__ uint4 pack_quad(float f0, float f1, float f2, float f3) {
    uint32_t h0, l0, h1, l1;
    cvtpair(f0, f1, h0, l0);
    cvtpair(f2, f3, h1, l1);
    return make_uint4(h0, h1, l0, l1);
}

// fp16 helpers
__device__ __forceinline__ uint32_t h2pack(float x, float y) {
    __half2 h = __floats2half2_rn(x, y);     // .x = x (low half)
    return *reinterpret_cast<uint32_t*>(&h);
}

__device__ __forceinline__ void h2split(float x, float y, uint32_t& hi, uint32_t& lo) {
    __half2 h = __floats2half2_rn(x, y);
    float2 b = __half22float2(h);
    __half2 l = __floats2half2_rn(x - b.x, y - b.y);
    hi = *reinterpret_cast<uint32_t*>(&h);
    lo = *reinterpret_cast<uint32_t*>(&l);
}

__device__ __forceinline__ uint4 quad_f16(float f0, float f1, float f2, float f3) {
    uint32_t h0, l0, h1, l1;
    h2split(f0, f1, h0, l0);
    h2split(f2, f3, h1, l1);
    return make_uint4(h0, h1, l0, l1);
}

__device__ __forceinline__ uint32_t s2u(const void* p) {
    uint32_t a;
    asm("{ .reg .u64 t; cvta.to.shared.u64 t, %1; cvt.u32.u64 %0, t; }" : "=r"(a) : "l"(p));
    return a;
}

__device__ __forceinline__ void cpa16(void* dst, const void* src) {
    asm volatile("cp.async.cg.shared.global [%0], [%1], 16;"
                 :: "r"(s2u(dst)), "l"(src) : "memory");
}
#define CPA_COMMIT() asm volatile("cp.async.commit_group;" ::: "memory")
#define CPA_WAIT0()  asm volatile("cp.async.wait_group 0;" ::: "memory")
#define CPA_WAIT1()  asm volatile("cp.async.wait_group 1;" ::: "memory")

__device__ __forceinline__ void mma_bf16(float* c, const uint32_t* a, const uint32_t* b) {
    asm volatile(
        "mma.sync.aligned.m16n8k16.row.col.f32.bf16.bf16.f32 "
        "{%0,%1,%2,%3}, {%4,%5,%6,%7}, {%8,%9}, {%0,%1,%2,%3};\n"
        : "+f"(c[0]), "+f"(c[1]), "+f"(c[2]), "+f"(c[3])
        : "r"(a[0]), "r"(a[1]), "r"(a[2]), "r"(a[3]),
          "r"(b[0]), "r"(b[1]));
}

__device__ __forceinline__ void mma_f16(float* c, const uint32_t* a, const uint32_t* b) {
    asm volatile(
        "mma.sync.aligned.m16n8k16.row.col.f32.f16.f16.f32 "
        "{%0,%1,%2,%3}, {%4,%5,%6,%7}, {%8,%9}, {%0,%1,%2,%3};\n"
        : "+f"(c[0]), "+f"(c[1]), "+f"(c[2]), "+f"(c[3])
        : "r"(a[0]), "r"(a[1]), "r"(a[2]), "r"(a[3]),
          "r"(b[0]), "r"(b[1]));
}

// ---------------- packs ----------------
__global__ void pack_pair16(const float* __restrict__ src, uint2* __restrict__ dst, int totalQ)
{
    int t = blockIdx.x * 256 + threadIdx.x;
    if (t >= totalQ) return;
    int r = t >> 9;           // 512 positions/row (K=2048)
    int G = t & 511;
    int ch = G >> 3, q = G & 7;
    int k0 = ch * 32 + (q >> 2) * 16 + (q & 3) * 2;
    const float* p = src + (size_t)r * DMODEL + k0;
    dst[t] = make_uint2(h2pack(p[0], p[1]), h2pack(p[8], p[9]));
}

__global__ void pack_quad16(const float* __restrict__ src, uint4* __restrict__ dst, int totalQ)
{
    int t = blockIdx.x * 256 + threadIdx.x;
    if (t >= totalQ) return;
    int r = t >> 9;
    int G = t & 511;
    int ch = G >> 3, q = G & 7;
    int k0 = ch * 32 + (q >> 2) * 16 + (q & 3) * 2;
    const float* p = src + (size_t)r * DMODEL + k0;
    dst[t] = quad_f16(p[0], p[1], p[8], p[9]);
}

// ---------------- V^T pack (bf16 quads): rows kv*128+d, K = sequence ----------------
__global__ void pack_vt()
{
    int t = blockIdx.x * 256 + threadIdx.x;   // 262144
    int q = t & 7, ch = (t >> 3) & 63;
    int d = (t >> 9) & 127, kv = t >> 16;
    int k0 = ch * 32 + (q >> 2) * 16 + (q & 3) * 2;
    const float* p = g_qkv + (size_t)k0 * QKVW + 2560 + kv * HD + d;
    vtq_[t] = pack_quad(p[0], p[QKVW], p[8 * QKVW], p[9 * QKVW]);
}

// =============================================================
// fp16 2-pass GEMM (NT): C = A * B^T.
// A = pair image (hi only), B = quad image (hi/lo); error = dropped aL*bH.
// Tile 128x128 x 32-K chunks; 256 thr, 8 warps (2Mx4N), warp 64x32.
// Smem/stage: A 128 rows x 24 u32 (16 data + pad), B 128 x 48 u32.
// =============================================================
#define SSTA 24
#define SSTB 48
#define STAGE_U32 (128 * SSTA + 128 * SSTB)   // 9216
#define GSMEM_BYTES (2 * STAGE_U32 * 4)       // 73728

__global__ void __launch_bounds__(256, 2)
gemm_f16(const uint2* __restrict__ Ap, const uint4* __restrict__ Bq,
         float* __restrict__ C, int ldc)
{
    const int bm = blockIdx.y, bn = blockIdx.x;
    const int nCh = 64;

    extern __shared__ uint32_t smu[];
    const int tid = threadIdx.x, lane = tid & 31, wid = tid >> 5;
    const int wm = (wid >> 2) * 64, wn = (wid & 3) * 32;
    const int g8 = lane >> 2, tig = lane & 3;

    const uint2* Ab = Ap + (size_t)bm * 128 * 512;
    const uint4* Bb = Bq + (size_t)bn * 128 * 512;

    float acc[4][4][4] = {};

    auto loadStage = [&](int ch, int st) {
        uint32_t* baseA = smu + st * STAGE_U32;
        uint32_t* baseB = baseA + 128 * SSTA;
#pragma unroll
        for (int i = 0; i < 6; i++) {
            int idx = tid + i * 256;            // 0..1535
            if (idx < 512) {                    // A: 128 rows x 4 x 16B
                int row = idx >> 2, part = idx & 3;
                cpa16(baseA + row * SSTA + part * 4, Ab + (size_t)row * 512 + ch * 8 + part * 2);
            } else {                            // B: 128 rows x 8 quads
                int j = idx - 512;
                int row = j >> 3, q = j & 7;
                cpa16(baseB + row * SSTB + q * 4, Bb + (size_t)row * 512 + ch * 8 + q);
            }
        }
        CPA_COMMIT();
    };

    auto compute = [&](int st) {
        const uint32_t* As = smu + st * STAGE_U32;
        const uint32_t* Bs = As + 128 * SSTA;
#pragma unroll
        for (int g = 0; g < 2; g++) {
            uint32_t aH[4][4], bH[4][2], bL[4][2];
#pragma unroll
            for (int mf = 0; mf < 4; mf++) {
                int r0 = wm + mf * 16 + g8;
                uint2 e0 = *(const uint2*)(As + r0 * SSTA + g * 8 + tig * 2);
                uint2 e1 = *(const uint2*)(As + (r0 + 8) * SSTA + g * 8 + tig * 2);
                aH[mf][0] = e0.x; aH[mf][1] = e1.x; aH[mf][2] = e0.y; aH[mf][3] = e1.y;
            }
#pragma unroll
            for (int nf = 0; nf < 4; nf++) {
                int n = wn + nf * 8 + g8;
                uint4 q = *(const uint4*)(Bs + n * SSTB + g * 16 + tig * 4);
                bH[nf][0] = q.x; bH[nf][1] = q.y;
                bL[nf][0] = q.z; bL[nf][1] = q.w;
            }
#pragma unroll
            for (int mf = 0; mf < 4; mf++)
#pragma unroll
                for (int nf = 0; nf < 4; nf++) {
                    mma_f16(acc[mf][nf], aH[mf], bL[nf]);
                    mma_f16(acc[mf][nf], aH[mf], bH[nf]);
                }
        }
    };

    loadStage(0, 0);
    for (int it = 0; it < nCh; ++it) {
        int cur = it & 1;
        if (it + 1 < nCh) { loadStage(it + 1, cur ^ 1); CPA_WAIT1(); }
        else              { CPA_WAIT0(); }
        __syncthreads();
        compute(cur);
        __syncthreads();
    }

    float* Cb = C + (size_t)bm * 128 * ldc + bn * 128;
#pragma unroll
    for (int mf = 0; mf < 4; mf++) {
        int row0 = wm + mf * 16 + g8, row1 = row0 + 8;
#pragma unroll
        for (int nf = 0; nf < 4; nf++) {
            int col = wn + nf * 8 + tig * 2;
            *(float2*)(Cb + (size_t)row0 * ldc + col) = make_float2(acc[mf][nf][0], acc[mf][nf][1]);
            *(float2*)(Cb + (size_t)row1 * ldc + col) = make_float2(acc[mf][nf][2], acc[mf][nf][3]);
        }
    }
}

// ---------------- RMSNorm + RoPE -> packed bf16 image ----------------
__global__ void rope2_kernel(const float* __restrict__ buf, int rowstride, int nheads,
                             const float* __restrict__ gain, float outscale,
                             uint4* __restrict__ img)
{
    __shared__ float stg[4][128];
    const int wib = threadIdx.x >> 5;
    const int w = blockIdx.x * 4 + wib;
    const int lane = threadIdx.x & 31;
    const int s = w / nheads, h = w % nheads;
    if (s >= S_LEN) return;

    const float* p = buf + (size_t)s * rowstride + h * HD;
    float2 u1 = *(const float2*)(p + 2 * lane);
    float2 u2 = *(const float2*)(p + 64 + 2 * lane);
    float ss = u1.x * u1.x + u1.y * u1.y + u2.x * u2.x + u2.y * u2.y;
#pragma unroll
    for (int off = 16; off; off >>= 1) ss += __shfl_xor_sync(0xffffffffu, ss, off);
    const float r = rsqrtf(ss * (1.f / 128.f) + 1.1920929e-07f);
    const float g = (gain ? gain[h] : 1.0f) * outscale;
    float x1a = u1.x * r, x1b = u1.y * r, x2a = u2.x * r, x2b = u2.y * r;
    const float kln = 9.210340371976184f / 128.f;
    float th0 = (float)s * expf(-(float)(4 * lane) * kln);
    float th1 = (float)s * expf(-(float)(4 * lane + 2) * kln);
    float c0, s0, c1, s1;
    sincosf(th0, &s0, &c0);
    sincosf(th1, &s1, &c1);
    stg[wib][2 * lane]          = (x1a * c0 + x2a * s0) * g;
    stg[wib][2 * lane + 1]      = (x1b * c1 + x2b * s1) * g;
    stg[wib][64 + 2 * lane]     = (x2a * c0 - x1a * s0) * g;
    stg[wib][64 + 2 * lane + 1] = (x2b * c1 - x1b * s1) * g;
    __syncwarp();
    int ch = lane >> 3, q = lane & 7;
    int k0 = ch * 32 + (q >> 2) * 16 + (q & 3) * 2;
    const float* sp = &stg[wib][0];
    img[(size_t)(h * S_LEN + s) * 32 + lane] =
        pack_quad(sp[k0], sp[k0 + 1], sp[k0 + 8], sp[k0 + 9]);
}

// =============================================================
// Fused flash attention + v-rejection + y pack (bf16 3-pass, ex2).
// Smem rows padded to 36 uint4 (conflict-free LDS.128).
// =============================================================
#define KSTRIDE 36
#define FL_SMEM (3 * 128 * KSTRIDE * 16)   // 221184

__global__ void __launch_bounds__(256, 1)
flash_attn()
{
    extern __shared__ uint4 fsm[];
    uint4* sQ = fsm;
    uint4* sK = fsm + 128 * KSTRIDE;
    uint4* sV = fsm + 2 * 128 * KSTRIDE;

    const int bid = blockIdx.x;
    const int qb = 15 - (bid >> 4);       // heavy tiles first
    const int h  = bid & 15;
    const int kv = h >> 2;
    const int tid = threadIdx.x, lane = tid & 31, wid = tid >> 5;
    const int g8 = lane >> 2, tig = lane & 3;
    const int mr = wid * 16;

    {
        const uint4* Qg = qq_ + ((size_t)h * S_LEN + qb * 128) * 32;
        const uint4* Kg = kq_ + ((size_t)kv * S_LEN) * 32;
#pragma unroll
        for (int i = 0; i < 16; i++) {
            int idx = tid + i * 256;
            int row = idx >> 5, q = idx & 31;
            cpa16(&sQ[row * KSTRIDE + q], &Qg[idx]);
            cpa16(&sK[row * KSTRIDE + q], &Kg[idx]);
        }
        CPA_COMMIT(); CPA_WAIT0(); __syncthreads();
    }

    float sAcc[16][4];
    float oAcc[16][4] = {};
    float mA = -INFINITY, mB = -INFINITY, lA = 0.f, lB = 0.f;

    for (int kb = 0; kb <= qb; kb++) {
#pragma unroll
        for (int i = 0; i < 16; i++) {
            int idx = tid + i * 256;
            int row = idx >> 5, lq = idx & 31;
            cpa16(&sV[row * KSTRIDE + lq],
                  &vtq_[((size_t)(kv * 128 + row)) * 512 + kb * 32 + lq]);
        }
        CPA_COMMIT();

#pragma unroll
        for (int nf = 0; nf < 16; nf++)
#pragma unroll
            for (int e = 0; e < 4; e++) sAcc[nf][e] = 0.f;
#pragma unroll
        for (int c = 0; c < 8; c++) {
            int qoff = (c >> 1) * 8 + (c & 1) * 4 + tig;
            uint4 q0 = sQ[(mr + g8) * KSTRIDE + qoff];
            uint4 q1 = sQ[(mr + g8 + 8) * KSTRIDE + qoff];
            uint32_t aH[4] = {q0.x, q1.x, q0.y, q1.y};
            uint32_t aL[4] = {q0.z, q1.z, q0.w, q1.w};
#pragma unroll
            for (int nf = 0; nf < 16; nf++) {
                uint4 kq4 = sK[(nf * 8 + g8) * KSTRIDE + qoff];
                uint32_t bH[2] = {kq4.x, kq4.y}, bL[2] = {kq4.z, kq4.w};
                mma_bf16(sAcc[nf], aL, bH);
                mma_bf16(sAcc[nf], aH, bL);
                mma_bf16(sAcc[nf], aH, bH);
            }
        }

        if (kb == qb) {
            int rA = mr + g8, rB = rA + 8;
#pragma unroll
            for (int nf = 0; nf < 16; nf++) {
                int c0 = nf * 8 + tig * 2;
                if (c0     > rA) sAcc[nf][0] = -INFINITY;
                if (c0 + 1 > rA) sAcc[nf][1] = -INFINITY;
                if (c0     > rB) sAcc[nf][2] = -INFINITY;
                if (c0 + 1 > rB) sAcc[nf][3] = -INFINITY;
            }
        }

        float mlA = -INFINITY, mlB = -INFINITY;
#pragma unroll
        for (int nf = 0; nf < 16; nf++) {
            mlA = fmaxf(mlA, fmaxf(sAcc[nf][0], sAcc[nf][1]));
            mlB = fmaxf(mlB, fmaxf(sAcc[nf][2], sAcc[nf][3]));
        }
        mlA = fmaxf(mlA, __shfl_xor_sync(0xffffffffu, mlA, 1));
        mlA = fmaxf(mlA, __shfl_xor_sync(0xffffffffu, mlA, 2));
        mlB = fmaxf(mlB, __shfl_xor_sync(0xffffffffu, mlB, 1));
        mlB = fmaxf(mlB, __shfl_xor_sync(0xffffffffu, mlB, 2));
        float mnA = fmaxf(mA, mlA), mnB = fmaxf(mB, mlB);
        float alA = ex2(mA - mnA), alB = ex2(mB - mnB);
        mA = mnA; mB = mnB;
        float rsA = 0.f, rsB = 0.f;
#pragma unroll
        for (int nf = 0; nf < 16; nf++) {
            float p0 = ex2(sAcc[nf][0] - mnA);
            float p1 = ex2(sAcc[nf][1] - mnA);
            float p2 = ex2(sAcc[nf][2] - mnB);
            float p3 = ex2(sAcc[nf][3] - mnB);
            sAcc[nf][0] = p0; sAcc[nf][1] = p1; sAcc[nf][2] = p2; sAcc[nf][3] = p3;
            rsA += p0 + p1; rsB += p2 + p3;
        }
        rsA += __shfl_xor_sync(0xffffffffu, rsA, 1);
        rsA += __shfl_xor_sync(0xffffffffu, rsA, 2);
        rsB += __shfl_xor_sync(0xffffffffu, rsB, 1);
        rsB += __shfl_xor_sync(0xffffffffu, rsB, 2);
        lA = lA * alA + rsA;
        lB = lB * alB + rsB;
#pragma unroll
        for (int nf = 0; nf < 16; nf++) {
            oAcc[nf][0] *= alA; oAcc[nf][1] *= alA;
            oAcc[nf][2] *= alB; oAcc[nf][3] *= alB;
        }

        CPA_WAIT0(); __syncthreads();

        if (kb < qb) {
            const uint4* Kg = kq_ + ((size_t)kv * S_LEN + (kb + 1) * 128) * 32;
#pragma unroll
            for (int i = 0; i < 16; i++) {
                int idx = tid + i * 256;
                int row = idx >> 5, q = idx & 31;
                cpa16(&sK[row * KSTRIDE + q], &Kg[idx]);
            }
            CPA_COMMIT();
        }

#pragma unroll
        for (int c = 0; c < 8; c++) {
            uint32_t aH[4], aL[4];
            cvtpair(sAcc[2 * c][0],     sAcc[2 * c][1],     aH[0], aL[0]);
            cvtpair(sAcc[2 * c][2],     sAcc[2 * c][3],     aH[1], aL[1]);
            cvtpair(sAcc[2 * c + 1][0], sAcc[2 * c + 1][1], aH[2], aL[2]);
            cvtpair(sAcc[2 * c + 1][2], sAcc[2 * c + 1][3], aH[3], aL[3]);
            int qoff = (c >> 1) * 8 + (c & 1) * 4 + tig;
#pragma unroll
            for (int nf = 0; nf < 16; nf++) {
                uint4 v4 = sV[(nf * 8 + g8) * KSTRIDE + qoff];
                uint32_t bH[2] = {v4.x, v4.y}, bL[2] = {v4.z, v4.w};
                mma_bf16(oAcc[nf], aL, bH);
                mma_bf16(oAcc[nf], aH, bL);
                mma_bf16(oAcc[nf], aH, bH);
            }
        }

        if (kb < qb) { CPA_WAIT0(); __syncthreads(); }
    }

    // ---- epilogue: normalize, stage, reject, pack y (fp16 hi-only) ----
    __syncthreads();
    float* Ob = (float*)sK;    // 128 x 132 fp32 fits in padded sK
    float invA = 1.f / lA, invB = 1.f / lB;
#pragma unroll
    for (int nf = 0; nf < 16; nf++) {
        int col = nf * 8 + tig * 2;
        Ob[(mr + g8) * 132 + col]         = oAcc[nf][0] * invA;
        Ob[(mr + g8) * 132 + col + 1]     = oAcc[nf][1] * invA;
        Ob[(mr + g8 + 8) * 132 + col]     = oAcc[nf][2] * invB;
        Ob[(mr + g8 + 8) * 132 + col + 1] = oAcc[nf][3] * invB;
    }
    __syncthreads();

    const float* gv = g_qkv + 2560 + kv * HD;
    for (int r16 = 0; r16 < 16; r16++) {
        int r = mr + r16;
        int sg = qb * 128 + r;
        float4 vv = *(const float4*)(gv + (size_t)sg * QKVW + lane * 4);
        float4 yy = *(float4*)(Ob + r * 132 + lane * 4);
        float vsq = vv.x * vv.x + vv.y * vv.y + vv.z * vv.z + vv.w * vv.w;
        float yv  = yy.x * vv.x + yy.y * vv.y + yy.z * vv.z + yy.w * vv.w;
#pragma unroll
        for (int off = 16; off; off >>= 1) {
            vsq += __shfl_xor_sync(0xffffffffu, vsq, off);
            yv  += __shfl_xor_sync(0xffffffffu, yv, off);
        }
        float mx = fmaxf(sqrtf(vsq), 1e-12f);
        float c2 = yv / (mx * mx);
        yy.x -= c2 * vv.x; yy.y -= c2 * vv.y; yy.z -= c2 * vv.z; yy.w -= c2 * vv.w;
        *(float4*)(Ob + r * 132 + lane * 4) = yy;
        __syncwarp();
        int ch = lane >> 3, ks = (lane >> 2) & 1, sq = lane & 3;
        int k0 = ch * 32 + ks * 16 + sq * 2;
        yq2_[(size_t)sg * 512 + (h * 4 + ch) * 8 + ks * 4 + sq] =
            make_uint2(h2pack(Ob[r * 132 + k0], Ob[r * 132 + k0 + 1]),
                       h2pack(Ob[r * 132 + k0 + 8], Ob[r * 132 + k0 + 9]));
        __syncwarp();
    }
}

// ---------------- v output transpose ----------------
__global__ void v_transpose_kernel(float* __restrict__ out)
{
    int idx = blockIdx.x * blockDim.x + threadIdx.x;
    if (idx < S_LEN * KVD / 4) {
        int f = idx * 4;
        int s = f / KVD, rem = f % KVD;
        int kvh = rem / HD, d = rem % HD;
        float4 val = *(const float4*)(g_qkv + (size_t)s * QKVW + 2560 + kvh * HD + d);
        *(float4*)(out + (size_t)kvh * S_LEN * HD + (size_t)s * HD + d) = val;
    }
}

// ---------------- launch ----------------
extern "C" void kernel_launch(void* const* d_in, const int* in_sizes, int n_in,
                              void* d_out, int out_size)
{
    int big[3], nbig = 0, med[2], nmed = 0, gidx = -1;
    for (int i = 0; i < n_in && i < 6; i++) {
        int sz = in_sizes[i];
        if (sz == NHEADS) gidx = i;
        else if (sz == S_LEN * KVD) { if (nmed < 2) med[nmed++] = i; }
        else { if (nbig < 3) big[nbig++] = i; }
    }
    int ix, iwq, iwk, iwv, iwp, ig;
    ig  = (gidx >= 0) ? gidx : 5;
    iwk = (nmed > 0) ? med[0] : 2;
    iwv = (nmed > 1) ? med[1] : 3;
    if (ig == 5) { ix = big[0]; iwq = big[1]; iwp = big[2]; }
    else         { iwp = big[0]; iwq = big[1]; ix = big[2]; }

    const float* x  = (const float*)d_in[ix];
    const float* Wq = (const float*)d_in[iwq];
    const float* Wk = (const float*)d_in[iwk];
    const float* Wv = (const float*)d_in[iwv];
    const float* Wp = (const float*)d_in[iwp];
    const float* qg = (const float*)d_in[ig];
    float* out = (float*)d_out;

    float* pqkv;
    cudaGetSymbolAddress((void**)&pqkv, g_qkv);
    uint2 *ix2, *iy2;
    uint4 *iwqkv, *iwpq, *iqq, *ikq;
    cudaGetSymbolAddress((void**)&ix2,   xq2_);
    cudaGetSymbolAddress((void**)&iy2,   yq2_);
    cudaGetSymbolAddress((void**)&iwqkv, wqkvq_);
    cudaGetSymbolAddress((void**)&iwpq,  wpq_);
    cudaGetSymbolAddress((void**)&iqq,   qq_);
    cudaGetSymbolAddress((void**)&ikq,   kq_);

    cudaFuncSetAttribute(gemm_f16, cudaFuncAttributeMaxDynamicSharedMemorySize, GSMEM_BYTES);
    cudaFuncSetAttribute(flash_attn, cudaFuncAttributeMaxDynamicSharedMemorySize, FL_SMEM);
    (void)cudaGetLastError();

    const float scale = 0.08838834764831845f;          // 1/sqrt(128)
    const float qscale = scale * 1.4426950408889634f;  // fold log2(e)

    // one-time packs
    pack_pair16<<<4096, 256>>>(x, ix2, 1048576);
    pack_quad16<<<4096, 256>>>(Wq, iwqkv, 1048576);
    pack_quad16<<<1024, 256>>>(Wk, iwqkv + (size_t)2048 * 512, 262144);
    pack_quad16<<<1024, 256>>>(Wv, iwqkv + (size_t)2560 * 512, 262144);
    pack_quad16<<<4096, 256>>>(Wp, iwpq, 1048576);

    // fused QKV projection (fp16 2-pass): g_qkv = x @ [Wq;Wk;Wv]^T
    gemm_f16<<<dim3(24, 16), 256, GSMEM_BYTES>>>(ix2, iwqkv, pqkv, QKVW);

    // rmsnorm + rope -> packed bf16 q/k ; V^T pack
    rope2_kernel<<<(S_LEN * NHEADS) / 4, 128>>>(pqkv, QKVW, NHEADS, qg, qscale, iqq);
    rope2_kernel<<<(S_LEN * KVH) / 4, 128>>>(pqkv + 2048, QKVW, KVH, nullptr, 1.0f, ikq);
    pack_vt<<<1024, 256>>>();

    // fused flash attention (bf16 3-pass, padded smem)
    flash_attn<<<256, 256, FL_SMEM>>>();

    // output projection (fp16 2-pass)
    gemm_f16<<<dim3(16, 16), 256, GSMEM_BYTES>>>(iy2, iwpq, out, DMODEL);

    // v second output
    if (out_size >= S_LEN * DMODEL + S_LEN * KVD)
        v_transpose_kernel<<<(S_LEN * KVD / 4 + 255) / 256, 256>>>(out + (size_t)S_LEN * DMODEL);
}